// round 4
// baseline (speedup 1.0000x reference)
#include <cuda_runtime.h>

#define EDGES   65536
#define NODESN  2048
#define DI      64
#define DOUT    64
#define EPSV    1e-6f
#define RCHUNK  128            // rows per scan block

// scratch (no cudaMalloc allowed)
__device__ int   g_si[EDGES];     // src index per edge
__device__ int   g_ti[EDGES];     // tgt index per edge
__device__ float g_aexp[EDGES];   // exp(a)  (mean shift algebraically cancels)
__device__ float g_asum[NODESN];  // per-target-node softmax denominator

// ---------------------------------------------------------------------------
// K1: one-hot -> index extraction. Reads the full 1 GB (src + tgt) as float4.
// Each thread owns 4 edges within a 128-row chunk; accumulates sum(n*v) and
// presence sum(v); the single chunk with presence==1 stores the int index.
// Blocks with blockIdx.y==0 additionally zero out[] and g_asum[] (consumed
// only by later kernels -> ordering guaranteed by kernel boundaries).
// grid: (64, 16) x 256 threads.
// ---------------------------------------------------------------------------
__global__ void __launch_bounds__(256) k_scan(const float4* __restrict__ src4,
                                              const float4* __restrict__ tgt4,
                                              float4* __restrict__ out4) {
    const int g4 = blockIdx.x * blockDim.x + threadIdx.x;   // float4 group id
    if (blockIdx.y == 0) {
        // zero out (32768 float4) and g_asum (512 float4): 16384 threads here
        out4[g4]         = make_float4(0.f, 0.f, 0.f, 0.f);
        out4[g4 + 16384] = make_float4(0.f, 0.f, 0.f, 0.f);
        if (g4 < NODESN / 4)
            ((float4*)g_asum)[g4] = make_float4(0.f, 0.f, 0.f, 0.f);
    }

    const int r0 = blockIdx.y * RCHUNK;                     // row chunk start
    const int stride4 = EDGES / 4;                          // 16384
    size_t base = (size_t)r0 * stride4 + g4;

    float4 ws = {0.f, 0.f, 0.f, 0.f}, wt = {0.f, 0.f, 0.f, 0.f};  // sum n*v
    float4 ps = {0.f, 0.f, 0.f, 0.f}, pt = {0.f, 0.f, 0.f, 0.f};  // sum v

#pragma unroll 8
    for (int n = 0; n < RCHUNK; ++n) {
        float fn = (float)(r0 + n);
        float4 vs = __ldcs(&src4[base]);
        float4 vt = __ldcs(&tgt4[base]);
        base += stride4;
        ws.x += vs.x * fn; ws.y += vs.y * fn; ws.z += vs.z * fn; ws.w += vs.w * fn;
        ps.x += vs.x;      ps.y += vs.y;      ps.z += vs.z;      ps.w += vs.w;
        wt.x += vt.x * fn; wt.y += vt.y * fn; wt.z += vt.z * fn; wt.w += vt.w * fn;
        pt.x += vt.x;      pt.y += vt.y;      pt.z += vt.z;      pt.w += vt.w;
    }
    int e0 = g4 * 4;
    if (ps.x > 0.5f) g_si[e0 + 0] = (int)(ws.x + 0.5f);
    if (ps.y > 0.5f) g_si[e0 + 1] = (int)(ws.y + 0.5f);
    if (ps.z > 0.5f) g_si[e0 + 2] = (int)(ws.z + 0.5f);
    if (ps.w > 0.5f) g_si[e0 + 3] = (int)(ws.w + 0.5f);
    if (pt.x > 0.5f) g_ti[e0 + 0] = (int)(wt.x + 0.5f);
    if (pt.y > 0.5f) g_ti[e0 + 1] = (int)(wt.y + 0.5f);
    if (pt.z > 0.5f) g_ti[e0 + 2] = (int)(wt.z + 0.5f);
    if (pt.w > 0.5f) g_ti[e0 + 3] = (int)(wt.w + 0.5f);
}

// ---------------------------------------------------------------------------
// K2: attention logit a = [x[s],x[t]].W_w + b_w, exp, per-target denominator.
// No mean subtraction (softmax shift-invariant; EPS perturbation ~2e-8 rel).
// ---------------------------------------------------------------------------
__global__ void __launch_bounds__(256) k_attn(const float* __restrict__ x,
                                              const float* __restrict__ Ww,
                                              const float* __restrict__ bw) {
    __shared__ float sWw[2 * DI];
    if (threadIdx.x < 2 * DI) sWw[threadIdx.x] = Ww[threadIdx.x];
    __syncthreads();

    int e = blockIdx.x * blockDim.x + threadIdx.x;
    int s = g_si[e];
    int t = g_ti[e];

    const float4* xs = (const float4*)(x + s * DI);
    const float4* xt = (const float4*)(x + t * DI);
    const float4* w0 = (const float4*)sWw;
    const float4* w1 = (const float4*)(sWw + DI);

    float acc = bw[0];
#pragma unroll
    for (int k = 0; k < DI / 4; ++k) {
        float4 a = xs[k], b = w0[k];
        acc += a.x * b.x + a.y * b.y + a.z * b.z + a.w * b.w;
        float4 c = xt[k], d = w1[k];
        acc += c.x * d.x + c.y * d.y + c.z * d.z + c.w * d.w;
    }
    float ae = expf(acc);
    g_aexp[e] = ae;
    atomicAdd(&g_asum[t], ae);
}

// ---------------------------------------------------------------------------
// K3: fused Y = relu(H @ W_f + b_f) * softmax weight, scatter to out.
// BE=64 edges per 64-thread block. hT[k][e] transposed in 32 KB smem.
// Each thread: 8 edges x 8 dims register tile -> 64 FFMA per
// (2 LDS.128 + 2 LDG.128), i.e. 16 FFMA per L1 op (2x R3).
// ---------------------------------------------------------------------------
#define BE 64
__global__ void __launch_bounds__(64) k_out(const float* __restrict__ x,
                                            const float* __restrict__ Wf,
                                            const float* __restrict__ bf,
                                            float* __restrict__ out) {
    __shared__ float hT[2 * DI * BE];   // hT[k*64 + e], k in [0,128)  (32 KB)
    __shared__ float we[BE];
    __shared__ int   tg[BE];

    const int tid = threadIdx.x;
    const int e0 = blockIdx.x * BE;

    // per-edge meta + stage both node rows for this thread's edge
    {
        int e = e0 + tid;
        int s = g_si[e];
        int t = g_ti[e];
        tg[tid] = t;
        we[tid] = g_aexp[e] / (g_asum[t] + EPSV);

        const float4* xs = (const float4*)(x + s * DI);
        const float4* xt = (const float4*)(x + t * DI);
#pragma unroll
        for (int i = 0; i < 16; ++i) {
            float4 v = xs[i];
            int k = i * 4;
            hT[(k + 0) * BE + tid] = v.x;
            hT[(k + 1) * BE + tid] = v.y;
            hT[(k + 2) * BE + tid] = v.z;
            hT[(k + 3) * BE + tid] = v.w;
        }
#pragma unroll
        for (int i = 0; i < 16; ++i) {
            float4 v = xt[i];
            int k = DI + i * 4;
            hT[(k + 0) * BE + tid] = v.x;
            hT[(k + 1) * BE + tid] = v.y;
            hT[(k + 2) * BE + tid] = v.z;
            hT[(k + 3) * BE + tid] = v.w;
        }
    }
    __syncthreads();

    const int eg = tid & 7;    // edges eg*8 .. eg*8+7
    const int dg = tid >> 3;   // dims  dg*8 .. dg*8+7

    float acc[8][8] = {};
    const float4* Wf4 = (const float4*)Wf;
#pragma unroll 4
    for (int k = 0; k < 2 * DI; ++k) {
        float4 h0 = *(const float4*)&hT[k * BE + eg * 8];
        float4 h1 = *(const float4*)&hT[k * BE + eg * 8 + 4];
        float4 w0 = __ldg(&Wf4[k * (DOUT / 4) + dg * 2]);
        float4 w1 = __ldg(&Wf4[k * (DOUT / 4) + dg * 2 + 1]);
        float hv[8] = {h0.x, h0.y, h0.z, h0.w, h1.x, h1.y, h1.z, h1.w};
        float wv[8] = {w0.x, w0.y, w0.z, w0.w, w1.x, w1.y, w1.z, w1.w};
#pragma unroll
        for (int i = 0; i < 8; ++i)
#pragma unroll
            for (int j = 0; j < 8; ++j)
                acc[i][j] += hv[i] * wv[j];
    }

    float4 b0 = __ldg((const float4*)&bf[dg * 8]);
    float4 b1 = __ldg((const float4*)&bf[dg * 8 + 4]);
    float bb[8] = {b0.x, b0.y, b0.z, b0.w, b1.x, b1.y, b1.z, b1.w};

#pragma unroll
    for (int i = 0; i < 8; ++i) {
        int el = eg * 8 + i;
        float w = we[el];
        float* op = out + tg[el] * DOUT + dg * 8;
#pragma unroll
        for (int j = 0; j < 8; ++j)
            atomicAdd(&op[j], fmaxf(acc[i][j] + bb[j], 0.0f) * w);
    }
}

// ---------------------------------------------------------------------------
extern "C" void kernel_launch(void* const* d_in, const int* in_sizes, int n_in,
                              void* d_out, int out_size) {
    const float* x   = (const float*)d_in[0];
    const float* src = (const float*)d_in[1];
    const float* tgt = (const float*)d_in[2];
    const float* Wf  = (const float*)d_in[3];
    const float* bf  = (const float*)d_in[4];
    const float* Ww  = (const float*)d_in[5];
    const float* bw  = (const float*)d_in[6];
    float* out = (float*)d_out;

    k_scan<<<dim3(EDGES / 4 / 256, NODESN / RCHUNK), 256>>>(
        (const float4*)src, (const float4*)tgt, (float4*)out);
    k_attn<<<EDGES / 256, 256>>>(x, Ww, bw);
    k_out<<<EDGES / BE, 64>>>(x, Wf, bf, out);
}

// round 5
// speedup vs baseline: 1.2192x; 1.2192x over previous
#include <cuda_runtime.h>

#define EDGES   65536
#define NODESN  2048
#define DI      64
#define DOUT    64
#define EPSV    1e-6f
#define RCHUNK  128            // rows per scan block

// scratch (no cudaMalloc allowed)
__device__ int   g_si[EDGES];          // src index per edge
__device__ int   g_ti[EDGES];          // tgt index per edge
__device__ float g_aexp[EDGES];        // exp(a)  (mean shift cancels in ratio)
__device__ float g_asum[NODESN];       // per-target softmax denominator
__device__ float g_P[NODESN * DOUT];   // x @ Wf_top
__device__ float g_Q[NODESN * DOUT];   // x @ Wf_bot
__device__ float g_u[NODESN];          // x . Ww_top
__device__ float g_v[NODESN];          // x . Ww_bot

// ---------------------------------------------------------------------------
// K0 (k_pre): per-node projections P,Q,u,v + zero out/g_asum.
// 32 blocks x 256 threads; block handles 64 nodes. Wf cached in smem (32KB),
// x tile transposed in smem (16KB). Thread = (node nl, 16-dim group dg).
// ---------------------------------------------------------------------------
__global__ void __launch_bounds__(256) k_pre(const float* __restrict__ x,
                                             const float* __restrict__ Wf,
                                             const float* __restrict__ Ww,
                                             float4* __restrict__ out4) {
    __shared__ float sW[2 * DI * DOUT];   // sW[k*64 + d], 32 KB
    __shared__ float sx[DI * 64];         // sx[k*64 + nl] (transposed), 16 KB

    const int tid = threadIdx.x;
    const int n0 = blockIdx.x * 64;

    // zero out (32768 float4) + g_asum (512 float4); consumed only post-scan
    {
        int gid = blockIdx.x * 256 + tid;           // 0..8191
#pragma unroll
        for (int i = 0; i < 4; ++i)
            out4[gid + i * 8192] = make_float4(0.f, 0.f, 0.f, 0.f);
        if (gid < NODESN / 4)
            ((float4*)g_asum)[gid] = make_float4(0.f, 0.f, 0.f, 0.f);
    }

    // load Wf into smem: 2048 float4, 8 per thread
    {
        const float4* Wf4 = (const float4*)Wf;
        float4* sW4 = (float4*)sW;
#pragma unroll
        for (int i = 0; i < 8; ++i)
            sW4[tid + i * 256] = Wf4[tid + i * 256];
    }
    // load x tile transposed: 1024 float4 reads, scatter to sx[k][nl]
    {
        const float4* x4 = (const float4*)x;
#pragma unroll
        for (int i = 0; i < 4; ++i) {
            int idx = tid + i * 256;          // 0..1023
            int nl = idx >> 4;                // node local
            int kq = idx & 15;                // float4 group within row
            float4 vv = x4[(n0 + nl) * (DI / 4) + kq];
            sx[(kq * 4 + 0) * 64 + nl] = vv.x;
            sx[(kq * 4 + 1) * 64 + nl] = vv.y;
            sx[(kq * 4 + 2) * 64 + nl] = vv.z;
            sx[(kq * 4 + 3) * 64 + nl] = vv.w;
        }
    }
    __syncthreads();

    const int nl = tid >> 2;          // 0..63
    const int dg = (tid & 3) * 16;    // dim base

    float accP[16] = {}, accQ[16] = {};
    const float4* sW4 = (const float4*)sW;
#pragma unroll 4
    for (int k = 0; k < DI; ++k) {
        float xv = sx[k * 64 + nl];
        int bP = (k * DOUT + dg) >> 2;
        int bQ = ((DI + k) * DOUT + dg) >> 2;
#pragma unroll
        for (int j = 0; j < 4; ++j) {
            float4 w = sW4[bP + j];
            accP[j * 4 + 0] += xv * w.x; accP[j * 4 + 1] += xv * w.y;
            accP[j * 4 + 2] += xv * w.z; accP[j * 4 + 3] += xv * w.w;
            float4 q = sW4[bQ + j];
            accQ[j * 4 + 0] += xv * q.x; accQ[j * 4 + 1] += xv * q.y;
            accQ[j * 4 + 2] += xv * q.z; accQ[j * 4 + 3] += xv * q.w;
        }
    }
    float4* P4 = (float4*)(g_P + (n0 + nl) * DOUT + dg);
    float4* Q4 = (float4*)(g_Q + (n0 + nl) * DOUT + dg);
#pragma unroll
    for (int j = 0; j < 4; ++j) {
        P4[j] = make_float4(accP[j*4+0], accP[j*4+1], accP[j*4+2], accP[j*4+3]);
        Q4[j] = make_float4(accQ[j*4+0], accQ[j*4+1], accQ[j*4+2], accQ[j*4+3]);
    }

    // u, v: one thread per node
    if (tid < 64) {
        float uu = 0.f, vv = 0.f;
#pragma unroll 8
        for (int k = 0; k < DI; ++k) {
            float xv = sx[k * 64 + tid];
            uu += xv * __ldg(&Ww[k]);
            vv += xv * __ldg(&Ww[DI + k]);
        }
        g_u[n0 + tid] = uu;
        g_v[n0 + tid] = vv;
    }
}

// ---------------------------------------------------------------------------
// K1 (k_scan): one-hot -> index extraction. Full 1 GB read, float4 streaming.
// Thread owns 4 edges within a 128-row chunk; accumulates sum(n*v) and
// presence sum(v); the unique chunk with presence==1 stores the index.
// ---------------------------------------------------------------------------
__global__ void __launch_bounds__(256) k_scan(const float4* __restrict__ src4,
                                              const float4* __restrict__ tgt4) {
    const int g4 = blockIdx.x * blockDim.x + threadIdx.x;
    const int r0 = blockIdx.y * RCHUNK;
    const int stride4 = EDGES / 4;                          // 16384
    size_t base = (size_t)r0 * stride4 + g4;

    float4 ws = {0.f,0.f,0.f,0.f}, wt = {0.f,0.f,0.f,0.f};  // sum n*v
    float4 ps = {0.f,0.f,0.f,0.f}, pt = {0.f,0.f,0.f,0.f};  // sum v

#pragma unroll 8
    for (int n = 0; n < RCHUNK; ++n) {
        float fn = (float)(r0 + n);
        float4 vs = __ldcs(&src4[base]);
        float4 vt = __ldcs(&tgt4[base]);
        base += stride4;
        ws.x += vs.x * fn; ws.y += vs.y * fn; ws.z += vs.z * fn; ws.w += vs.w * fn;
        ps.x += vs.x;      ps.y += vs.y;      ps.z += vs.z;      ps.w += vs.w;
        wt.x += vt.x * fn; wt.y += vt.y * fn; wt.z += vt.z * fn; wt.w += vt.w * fn;
        pt.x += vt.x;      pt.y += vt.y;      pt.z += vt.z;      pt.w += vt.w;
    }
    int e0 = g4 * 4;
    if (ps.x > 0.5f) g_si[e0 + 0] = (int)(ws.x + 0.5f);
    if (ps.y > 0.5f) g_si[e0 + 1] = (int)(ws.y + 0.5f);
    if (ps.z > 0.5f) g_si[e0 + 2] = (int)(ws.z + 0.5f);
    if (ps.w > 0.5f) g_si[e0 + 3] = (int)(ws.w + 0.5f);
    if (pt.x > 0.5f) g_ti[e0 + 0] = (int)(wt.x + 0.5f);
    if (pt.y > 0.5f) g_ti[e0 + 1] = (int)(wt.y + 0.5f);
    if (pt.z > 0.5f) g_ti[e0 + 2] = (int)(wt.z + 0.5f);
    if (pt.w > 0.5f) g_ti[e0 + 3] = (int)(wt.w + 0.5f);
}

// ---------------------------------------------------------------------------
// K2 (k_edge): a[e] = u[s]+v[t]+bw; exp; per-target denominator.
// No mean subtraction (softmax shift-invariant; EPS perturbation ~2e-8 rel).
// ---------------------------------------------------------------------------
__global__ void __launch_bounds__(256) k_edge(const float* __restrict__ bw) {
    int e = blockIdx.x * blockDim.x + threadIdx.x;
    int s = g_si[e];
    int t = g_ti[e];
    float ae = expf(g_u[s] + g_v[t] + bw[0]);
    g_aexp[e] = ae;
    atomicAdd(&g_asum[t], ae);
}

// ---------------------------------------------------------------------------
// K3 (k_out): y = relu(P[s]+Q[t]+bf) * softmax weight, scatter via
// vector red.global.v2.f32. One warp per edge, one lane per 2 dims.
// ---------------------------------------------------------------------------
__global__ void __launch_bounds__(256) k_out(const float* __restrict__ bf,
                                             float* __restrict__ out) {
    int gid = blockIdx.x * blockDim.x + threadIdx.x;
    int e    = gid >> 5;
    int lane = gid & 31;
    int s = g_si[e];
    int t = g_ti[e];
    float w = g_aexp[e] / (g_asum[t] + EPSV);
    float2 p = ((const float2*)g_P)[s * 32 + lane];
    float2 q = ((const float2*)g_Q)[t * 32 + lane];
    float2 b = __ldg(&((const float2*)bf)[lane]);
    float2 y;
    y.x = fmaxf(p.x + q.x + b.x, 0.0f) * w;
    y.y = fmaxf(p.y + q.y + b.y, 0.0f) * w;
    atomicAdd((float2*)(out + t * DOUT + lane * 2), y);
}

// ---------------------------------------------------------------------------
extern "C" void kernel_launch(void* const* d_in, const int* in_sizes, int n_in,
                              void* d_out, int out_size) {
    const float* x   = (const float*)d_in[0];
    const float* src = (const float*)d_in[1];
    const float* tgt = (const float*)d_in[2];
    const float* Wf  = (const float*)d_in[3];
    const float* bf  = (const float*)d_in[4];
    const float* Ww  = (const float*)d_in[5];
    const float* bw  = (const float*)d_in[6];
    float* out = (float*)d_out;

    k_pre<<<NODESN / 64, 256>>>(x, Wf, Ww, (float4*)out);
    k_scan<<<dim3(EDGES / 4 / 256, NODESN / RCHUNK), 256>>>(
        (const float4*)src, (const float4*)tgt);
    k_edge<<<EDGES / 256, 256>>>(bw);
    k_out<<<EDGES * 32 / 256, 256>>>(bf, out);
}

// round 6
// speedup vs baseline: 1.3827x; 1.1341x over previous
#include <cuda_runtime.h>

#define EDGES   65536
#define NODESN  2048
#define DI      64
#define DOUT    64
#define EPSV    1e-6f
#define RCHUNK  32             // rows per scan tile (4096 tiles -> ~99% slot util)

// scratch (no cudaMalloc allowed)
__device__ int   g_si[EDGES];          // src index per edge
__device__ int   g_ti[EDGES];          // tgt index per edge
__device__ float g_asum[NODESN];       // per-target softmax denominator
__device__ float g_num[NODESN * DOUT]; // per-target weighted-numerator accum
__device__ float g_P[NODESN * DOUT];   // x @ Wf_top
__device__ float g_Q[NODESN * DOUT];   // x @ Wf_bot
__device__ float g_u[NODESN];          // x . Ww_top
__device__ float g_v[NODESN];          // x . Ww_bot

// ---------------------------------------------------------------------------
// K0 (k_pre): per-node projections P,Q,u,v + zero g_num/g_asum.
// 32 blocks x 256 threads; runs on a side stream overlapped with k_scan
// (independent: touches neither src/tgt nor g_si/g_ti).
// ---------------------------------------------------------------------------
__global__ void __launch_bounds__(256) k_pre(const float* __restrict__ x,
                                             const float* __restrict__ Wf,
                                             const float* __restrict__ Ww) {
    __shared__ float sW[2 * DI * DOUT];   // sW[k*64 + d], 32 KB
    __shared__ float sx[DI * 64];         // sx[k*64 + nl] (transposed), 16 KB

    const int tid = threadIdx.x;
    const int n0 = blockIdx.x * 64;

    // zero g_num (32768 float4) + g_asum (512 float4)
    {
        int gid = blockIdx.x * 256 + tid;           // 0..8191
        float4* num4 = (float4*)g_num;
#pragma unroll
        for (int i = 0; i < 4; ++i)
            num4[gid + i * 8192] = make_float4(0.f, 0.f, 0.f, 0.f);
        if (gid < NODESN / 4)
            ((float4*)g_asum)[gid] = make_float4(0.f, 0.f, 0.f, 0.f);
    }

    // load Wf into smem: 2048 float4, 8 per thread
    {
        const float4* Wf4 = (const float4*)Wf;
        float4* sW4 = (float4*)sW;
#pragma unroll
        for (int i = 0; i < 8; ++i)
            sW4[tid + i * 256] = Wf4[tid + i * 256];
    }
    // load x tile transposed: 1024 float4 reads, scatter to sx[k][nl]
    {
        const float4* x4 = (const float4*)x;
#pragma unroll
        for (int i = 0; i < 4; ++i) {
            int idx = tid + i * 256;          // 0..1023
            int nl = idx >> 4;                // node local
            int kq = idx & 15;                // float4 group within row
            float4 vv = x4[(n0 + nl) * (DI / 4) + kq];
            sx[(kq * 4 + 0) * 64 + nl] = vv.x;
            sx[(kq * 4 + 1) * 64 + nl] = vv.y;
            sx[(kq * 4 + 2) * 64 + nl] = vv.z;
            sx[(kq * 4 + 3) * 64 + nl] = vv.w;
        }
    }
    __syncthreads();

    const int nl = tid >> 2;          // 0..63
    const int dg = (tid & 3) * 16;    // dim base

    float accP[16] = {}, accQ[16] = {};
    const float4* sW4 = (const float4*)sW;
#pragma unroll 4
    for (int k = 0; k < DI; ++k) {
        float xv = sx[k * 64 + nl];
        int bP = (k * DOUT + dg) >> 2;
        int bQ = ((DI + k) * DOUT + dg) >> 2;
#pragma unroll
        for (int j = 0; j < 4; ++j) {
            float4 w = sW4[bP + j];
            accP[j * 4 + 0] += xv * w.x; accP[j * 4 + 1] += xv * w.y;
            accP[j * 4 + 2] += xv * w.z; accP[j * 4 + 3] += xv * w.w;
            float4 q = sW4[bQ + j];
            accQ[j * 4 + 0] += xv * q.x; accQ[j * 4 + 1] += xv * q.y;
            accQ[j * 4 + 2] += xv * q.z; accQ[j * 4 + 3] += xv * q.w;
        }
    }
    float4* P4 = (float4*)(g_P + (n0 + nl) * DOUT + dg);
    float4* Q4 = (float4*)(g_Q + (n0 + nl) * DOUT + dg);
#pragma unroll
    for (int j = 0; j < 4; ++j) {
        P4[j] = make_float4(accP[j*4+0], accP[j*4+1], accP[j*4+2], accP[j*4+3]);
        Q4[j] = make_float4(accQ[j*4+0], accQ[j*4+1], accQ[j*4+2], accQ[j*4+3]);
    }

    // u, v: one thread per node
    if (tid < 64) {
        float uu = 0.f, vv = 0.f;
#pragma unroll 8
        for (int k = 0; k < DI; ++k) {
            float xv = sx[k * 64 + tid];
            uu += xv * __ldg(&Ww[k]);
            vv += xv * __ldg(&Ww[DI + k]);
        }
        g_u[n0 + tid] = uu;
        g_v[n0 + tid] = vv;
    }
}

// ---------------------------------------------------------------------------
// K1 (k_scan): one-hot -> index extraction. Full 1 GB read, float4 streaming.
// Thread owns 4 edges within a 32-row chunk; accumulates sum(n*v) and
// presence sum(v); the unique chunk with presence==1 stores the index.
// grid (64, 64) = 4096 small tiles -> ~7 even waves at 4 blocks/SM.
// ---------------------------------------------------------------------------
__global__ void __launch_bounds__(256) k_scan(const float4* __restrict__ src4,
                                              const float4* __restrict__ tgt4) {
    const int g4 = blockIdx.x * blockDim.x + threadIdx.x;
    const int r0 = blockIdx.y * RCHUNK;
    const int stride4 = EDGES / 4;                          // 16384
    size_t base = (size_t)r0 * stride4 + g4;

    float4 ws = {0.f,0.f,0.f,0.f}, wt = {0.f,0.f,0.f,0.f};  // sum n*v
    float4 ps = {0.f,0.f,0.f,0.f}, pt = {0.f,0.f,0.f,0.f};  // sum v

#pragma unroll 8
    for (int n = 0; n < RCHUNK; ++n) {
        float fn = (float)(r0 + n);
        float4 vs = __ldcs(&src4[base]);
        float4 vt = __ldcs(&tgt4[base]);
        base += stride4;
        ws.x += vs.x * fn; ws.y += vs.y * fn; ws.z += vs.z * fn; ws.w += vs.w * fn;
        ps.x += vs.x;      ps.y += vs.y;      ps.z += vs.z;      ps.w += vs.w;
        wt.x += vt.x * fn; wt.y += vt.y * fn; wt.z += vt.z * fn; wt.w += vt.w * fn;
        pt.x += vt.x;      pt.y += vt.y;      pt.z += vt.z;      pt.w += vt.w;
    }
    int e0 = g4 * 4;
    if (ps.x > 0.5f) g_si[e0 + 0] = (int)(ws.x + 0.5f);
    if (ps.y > 0.5f) g_si[e0 + 1] = (int)(ws.y + 0.5f);
    if (ps.z > 0.5f) g_si[e0 + 2] = (int)(ws.z + 0.5f);
    if (ps.w > 0.5f) g_si[e0 + 3] = (int)(ws.w + 0.5f);
    if (pt.x > 0.5f) g_ti[e0 + 0] = (int)(wt.x + 0.5f);
    if (pt.y > 0.5f) g_ti[e0 + 1] = (int)(wt.y + 0.5f);
    if (pt.z > 0.5f) g_ti[e0 + 2] = (int)(wt.z + 0.5f);
    if (pt.w > 0.5f) g_ti[e0 + 3] = (int)(wt.w + 0.5f);
}

// ---------------------------------------------------------------------------
// K2 (k_edge): one warp per edge. ae = exp(u[s]+v[t]+bw);
// num[t][:] += ae * relu(P[s]+Q[t]+bf);  asum[t] += ae.
// No mean subtraction (softmax shift-invariant; EPS perturbation ~2e-8 rel).
// ---------------------------------------------------------------------------
__global__ void __launch_bounds__(256) k_edge(const float* __restrict__ bf,
                                              const float* __restrict__ bw) {
    int gid  = blockIdx.x * blockDim.x + threadIdx.x;
    int e    = gid >> 5;
    int lane = gid & 31;
    int s = g_si[e];
    int t = g_ti[e];
    float ae = expf(g_u[s] + g_v[t] + bw[0]);

    float2 p = ((const float2*)g_P)[s * 32 + lane];
    float2 q = ((const float2*)g_Q)[t * 32 + lane];
    float2 b = __ldg(&((const float2*)bf)[lane]);
    float2 y;
    y.x = fmaxf(p.x + q.x + b.x, 0.0f) * ae;
    y.y = fmaxf(p.y + q.y + b.y, 0.0f) * ae;
    atomicAdd((float2*)(g_num + t * DOUT + lane * 2), y);
    if (lane == 0) atomicAdd(&g_asum[t], ae);
}

// ---------------------------------------------------------------------------
// K3 (k_div): out = num / (asum + eps). Fully overwrites d_out.
// ---------------------------------------------------------------------------
__global__ void __launch_bounds__(256) k_div(float4* __restrict__ out4) {
    int i = blockIdx.x * blockDim.x + threadIdx.x;   // 0..32767 float4
    float inv = 1.0f / (g_asum[i >> 4] + EPSV);
    float4 n = ((const float4*)g_num)[i];
    out4[i] = make_float4(n.x * inv, n.y * inv, n.z * inv, n.w * inv);
}

// ---------------------------------------------------------------------------
extern "C" void kernel_launch(void* const* d_in, const int* in_sizes, int n_in,
                              void* d_out, int out_size) {
    const float* x   = (const float*)d_in[0];
    const float* src = (const float*)d_in[1];
    const float* tgt = (const float*)d_in[2];
    const float* Wf  = (const float*)d_in[3];
    const float* bf  = (const float*)d_in[4];
    const float* Ww  = (const float*)d_in[5];
    const float* bw  = (const float*)d_in[6];
    float* out = (float*)d_out;

    // side stream + events, created once on the (uncaptured) first call
    static cudaStream_t s2 = nullptr;
    static cudaEvent_t ev_fork = nullptr, ev_join = nullptr;
    if (s2 == nullptr) {
        cudaStreamCreateWithFlags(&s2, cudaStreamNonBlocking);
        cudaEventCreateWithFlags(&ev_fork, cudaEventDisableTiming);
        cudaEventCreateWithFlags(&ev_join, cudaEventDisableTiming);
    }

    // fork: k_pre (projections + zeroing) overlaps the HBM-bound scan
    cudaEventRecord(ev_fork, 0);
    cudaStreamWaitEvent(s2, ev_fork, 0);
    k_pre<<<NODESN / 64, 256, 0, s2>>>(x, Wf, Ww);
    cudaEventRecord(ev_join, s2);

    k_scan<<<dim3(EDGES / 4 / 256, NODESN / RCHUNK), 256>>>(
        (const float4*)src, (const float4*)tgt);

    // join: edge pass needs both scan (indices) and pre (P,Q,u,v,zeros)
    cudaStreamWaitEvent(0, ev_join, 0);
    k_edge<<<EDGES * 32 / 256, 256>>>(bf, bw);
    k_div<<<NODESN * DOUT / 4 / 256, 256>>>((float4*)out);
}